// round 16
// baseline (speedup 1.0000x reference)
#include <cuda_runtime.h>
#include <cuda_fp16.h>
#include <cstdint>
#include <math.h>

typedef unsigned int u32;
typedef unsigned long long u64;

#define SEQ 2048
#define HIDDEN 2048
#define NUM_HEADS 16
#define NUM_KV_HEADS 8
#define HEAD_DIM 128
#define Q_SIZE 2048
#define KV_SIZE 1024
#define QKV_COLS 4096
#define V_OFF 3072

// -------- scratch (static device memory; no allocation) --------
__device__ __half g_norm_h[SEQ * HIDDEN];
__device__ float2 g_rope[SEQ * 64];
__device__ __half g_q_h[SEQ * Q_SIZE];
__device__ __half g_k_h[SEQ * KV_SIZE];
__device__ __half g_v_h[SEQ * KV_SIZE];
__device__ __half g_att_h[SEQ * Q_SIZE];
__device__ __half g_wq_h[QKV_COLS * HIDDEN];
__device__ __half g_wo_h[HIDDEN * Q_SIZE];

// ======================= helpers =======================
__device__ __forceinline__ u32 smem_u32(const void* p) {
    u32 a;
    asm("{ .reg .u64 t; cvta.to.shared.u64 t, %1; cvt.u32.u64 %0, t; }" : "=r"(a) : "l"(p));
    return a;
}
__device__ __forceinline__ void ldsm_x4(u32& r0, u32& r1, u32& r2, u32& r3, u32 a) {
    asm volatile("ldmatrix.sync.aligned.m8n8.x4.shared.b16 {%0,%1,%2,%3}, [%4];"
                 : "=r"(r0), "=r"(r1), "=r"(r2), "=r"(r3) : "r"(a));
}
__device__ __forceinline__ void ldsm_x2(u32& r0, u32& r1, u32 a) {
    asm volatile("ldmatrix.sync.aligned.m8n8.x2.shared.b16 {%0,%1}, [%2];"
                 : "=r"(r0), "=r"(r1) : "r"(a));
}
__device__ __forceinline__ void ldsm_x4t(u32& r0, u32& r1, u32& r2, u32& r3, u32 a) {
    asm volatile("ldmatrix.sync.aligned.m8n8.x4.trans.shared.b16 {%0,%1,%2,%3}, [%4];"
                 : "=r"(r0), "=r"(r1), "=r"(r2), "=r"(r3) : "r"(a));
}
__device__ __forceinline__ void mma_f16(float* c, const u32* a, const u32* b) {
    asm volatile("mma.sync.aligned.m16n8k16.row.col.f32.f16.f16.f32 "
                 "{%0,%1,%2,%3}, {%4,%5,%6,%7}, {%8,%9}, {%0,%1,%2,%3};"
                 : "+f"(c[0]), "+f"(c[1]), "+f"(c[2]), "+f"(c[3])
                 : "r"(a[0]), "r"(a[1]), "r"(a[2]), "r"(a[3]), "r"(b[0]), "r"(b[1]));
}
#define CP_COMMIT() asm volatile("cp.async.commit_group;" ::: "memory")
#define CP_WAIT(n)  asm volatile("cp.async.wait_group %0;" :: "n"(n) : "memory")
__device__ __forceinline__ void cp16(u32 d, const void* s) {
    asm volatile("cp.async.cg.shared.global [%0], [%1], 16;" :: "r"(d), "l"(s));
}
__device__ __forceinline__ u32 packh(float x, float y) {
    __half2 t = __floats2half2_rn(x, y);
    return *(u32*)&t;
}

// ======================= fp32 -> single fp16 convert =======================
__global__ __launch_bounds__(256) void convh_kernel(
    const float* __restrict__ x, __half* __restrict__ y, int n4)
{
    int i = blockIdx.x * 256 + threadIdx.x;
    if (i >= n4) return;
    float4 v = ((const float4*)x)[i];
    y[4*i+0] = __float2half_rn(v.x);
    y[4*i+1] = __float2half_rn(v.y);
    y[4*i+2] = __float2half_rn(v.z);
    y[4*i+3] = __float2half_rn(v.w);
}

// ======================= RMSNorm -> single fp16 =======================
__global__ __launch_bounds__(256) void rmsnorm_kernel(
    const float* __restrict__ x, const float* __restrict__ w,
    __half* __restrict__ oh)
{
    int row = blockIdx.x;
    int t = threadIdx.x;
    const float4* xr = (const float4*)(x + (size_t)row * HIDDEN);
    float4 v0 = xr[t];
    float4 v1 = xr[t + 256];
    float ss = v0.x*v0.x + v0.y*v0.y + v0.z*v0.z + v0.w*v0.w
             + v1.x*v1.x + v1.y*v1.y + v1.z*v1.z + v1.w*v1.w;
    #pragma unroll
    for (int o = 16; o; o >>= 1) ss += __shfl_xor_sync(0xffffffffu, ss, o);
    __shared__ float wsum[8];
    if ((t & 31) == 0) wsum[t >> 5] = ss;
    __syncthreads();
    float tot = wsum[0] + wsum[1] + wsum[2] + wsum[3]
              + wsum[4] + wsum[5] + wsum[6] + wsum[7];
    float inv = rsqrtf(tot * (1.0f / HIDDEN) + 1e-6f);
    const float4* wr = (const float4*)w;
    float4 w0 = wr[t], w1 = wr[t + 256];
    size_t base = (size_t)row * HIDDEN;
    u32* oh32 = (u32*)(oh + base);
    oh32[t*2]         = packh(v0.x*inv*w0.x, v0.y*inv*w0.y);
    oh32[t*2+1]       = packh(v0.z*inv*w0.z, v0.w*inv*w0.w);
    oh32[(t+256)*2]   = packh(v1.x*inv*w1.x, v1.y*inv*w1.y);
    oh32[(t+256)*2+1] = packh(v1.z*inv*w1.z, v1.w*inv*w1.w);
}

// ======================= RoPE cos/sin table (once) =======================
__global__ __launch_bounds__(64) void rope_table_kernel(
    const int* __restrict__ positions, float2* __restrict__ tab)
{
    int s = blockIdx.x, j = threadIdx.x;
    float inv_freq = (float)pow(10000.0, -(double)(2 * j) / 128.0);
    float fr = (float)positions[s] * inv_freq;
    double sd, cd;
    sincos((double)fr, &sd, &cd);
    tab[s * 64 + j] = make_float2((float)cd, (float)sd);
}

// ===== mma.sync fp16 GEMM: C[M,N] = A[M,K] @ B[N,K]^T =====
// CTA tile 128x128, BK=32, 8 warps, cp.async double buffer, occ 2.
// EPI=0: fp32 C out (O-proj). EPI=1: fused qkv epilogue — quantize tile to
// fp16 in smem (same quantization point as the old qkv_h store), then apply
// rope + per-head RMSNorm for q/k head-blocks, plain copy for v-blocks.
#define BK 32
#define LDT 40
#define TILE_B (128 * LDT * 2)
#define STAGE_B (2 * TILE_B)          // A | B = 20480
#define GSMEM (2 * STAGE_B)           // 40960
#define SER 272                        // epilogue smem row stride (16-aligned; 34816 <= GSMEM)

__device__ __forceinline__ void load_stage_async(
    u32 sdst, const __half* __restrict__ A, const __half* __restrict__ B,
    int m0, int n0, int kc, int K, int tid)
{
    #pragma unroll
    for (int i = 0; i < 4; ++i) {
        int c = tid + i * 256;
        int tile = c >> 9;
        int rem = c & 511;
        int row = rem >> 2;
        int col8 = (rem & 3) * 8;
        const __half* src = tile ? B : A;
        int gr = (tile ? n0 : m0) + row;
        cp16(sdst + tile * TILE_B + row * (LDT * 2) + col8 * 2,
             (const void*)(src + (size_t)gr * K + kc + col8));
    }
}

template<int EPI>
__global__ __launch_bounds__(256, 2) void gemm_mma_kernel(
    const __half* __restrict__ A, const __half* __restrict__ B,
    float* __restrict__ C, int M, int N, int K,
    const float2* __restrict__ tab, const float* __restrict__ qw,
    const float* __restrict__ kw,
    __half* __restrict__ qh, __half* __restrict__ kh, __half* __restrict__ vh)
{
    extern __shared__ __align__(16) char sm[];
    const u32 smb = smem_u32(sm);
    const int tid = threadIdx.x, wid = tid >> 5, lane = tid & 31;
    const int m0 = blockIdx.y * 128, n0 = blockIdx.x * 128;
    const int wm = wid >> 2, wn = wid & 3;

    float acc[4][4][4];
    #pragma unroll
    for (int a = 0; a < 4; ++a)
        #pragma unroll
        for (int b = 0; b < 4; ++b)
            #pragma unroll
            for (int d = 0; d < 4; ++d) acc[a][b][d] = 0.0f;

    const int NC = K / BK;

    load_stage_async(smb, A, B, m0, n0, 0, K, tid);
    CP_COMMIT();

    const u32 a_base = (u32)((wm * 64 + (lane & 15)) * (LDT * 2));
    const u32 a_koff = (u32)(((lane >> 4) << 3) * 2);
    const u32 b_base = (u32)((wn * 32 + (lane & 7)) * (LDT * 2));
    const u32 b_koff = (u32)((((lane >> 3) & 1) << 3) * 2);

    for (int c = 0; c < NC; ++c) {
        if (c + 1 < NC) {
            load_stage_async(smb + ((c + 1) & 1) * STAGE_B, A, B,
                             m0, n0, (c + 1) * BK, K, tid);
            CP_COMMIT();
            CP_WAIT(1);
        } else {
            CP_WAIT(0);
        }
        __syncthreads();

        const u32 st = smb + (c & 1) * STAGE_B;
        const u32 sA = st, sB = st + TILE_B;

        #pragma unroll
        for (int ks = 0; ks < 2; ++ks) {
            const u32 kb = (u32)(ks * 16 * 2);
            u32 bh[4][2];
            #pragma unroll
            for (int nf = 0; nf < 4; ++nf)
                ldsm_x2(bh[nf][0], bh[nf][1],
                        sB + b_base + nf * 8 * (LDT * 2) + kb + b_koff);
            #pragma unroll
            for (int mh = 0; mh < 2; ++mh) {
                u32 ah[2][4];
                #pragma unroll
                for (int m2 = 0; m2 < 2; ++m2)
                    ldsm_x4(ah[m2][0], ah[m2][1], ah[m2][2], ah[m2][3],
                            sA + a_base + (mh * 2 + m2) * 16 * (LDT * 2) + kb + a_koff);
                #pragma unroll
                for (int m2 = 0; m2 < 2; ++m2)
                    #pragma unroll
                    for (int nf = 0; nf < 4; ++nf)
                        mma_f16(acc[mh * 2 + m2][nf], ah[m2], bh[nf]);
            }
        }
        __syncthreads();
    }

    const int gro = lane >> 2, tq = lane & 3;

    if (EPI == 0) {
        #pragma unroll
        for (int mf = 0; mf < 4; ++mf) {
            #pragma unroll
            for (int nf = 0; nf < 4; ++nf) {
                int r = m0 + wm * 64 + mf * 16 + gro;
                int col = n0 + wn * 32 + nf * 8 + tq * 2;
                *(float2*)&C[(size_t)r * N + col]       = make_float2(acc[mf][nf][0], acc[mf][nf][1]);
                *(float2*)&C[(size_t)(r + 8) * N + col] = make_float2(acc[mf][nf][2], acc[mf][nf][3]);
            }
        }
    } else {
        // ---- stage tile as fp16 in smem (the quantization point) ----
        #pragma unroll
        for (int mf = 0; mf < 4; ++mf) {
            #pragma unroll
            for (int nf = 0; nf < 4; ++nf) {
                int r = wm * 64 + mf * 16 + gro;
                int col = wn * 32 + nf * 8 + tq * 2;
                *(u32*)(sm + r * SER + col * 2)       = packh(acc[mf][nf][0], acc[mf][nf][1]);
                *(u32*)(sm + (r + 8) * SER + col * 2) = packh(acc[mf][nf][2], acc[mf][nf][3]);
            }
        }
        __syncthreads();

        const int hidx = n0 >> 7;    // 0..15 q, 16..23 k, 24..31 v
        if (hidx >= 24) {
            // v block: plain copy to compact layout
            const int kvh = hidx - 24;
            #pragma unroll
            for (int it = 0; it < 8; ++it) {
                int c = tid + it * 256;          // 0..2047 16B chunks
                int row = c >> 4, ch = c & 15;
                uint4 v = *(uint4*)(sm + row * SER + ch * 16);
                *(uint4*)&vh[(size_t)(m0 + row) * KV_SIZE + kvh * HEAD_DIM + ch * 8] = v;
            }
        } else {
            // q/k block: rope + per-head rmsnorm. 2 threads per row.
            const bool isq = hidx < 16;
            const int row = tid >> 1, hf = tid & 1;
            const int s = m0 + row;
            const char* rowp = sm + row * SER;
            // pass 1: sum of squares of this thread's 64 outputs
            float ss = 0.0f;
            #pragma unroll 8
            for (int j = 0; j < 64; ++j) {
                float x1 = __half2float(*(const __half*)(rowp + j * 2));
                float x2 = __half2float(*(const __half*)(rowp + (j + 64) * 2));
                float2 cssn = tab[(size_t)s * 64 + j];
                float v = hf ? (x2 * cssn.x + x1 * cssn.y)
                             : (x1 * cssn.x - x2 * cssn.y);
                ss += v * v;
            }
            ss += __shfl_xor_sync(0xffffffffu, ss, 1);
            float inv = rsqrtf(ss * (1.0f / HEAD_DIM) + 1e-6f);
            const float* wp = (isq ? qw : kw) + hf * 64;
            __half* dst = isq
                ? (qh + (size_t)s * Q_SIZE + hidx * HEAD_DIM + hf * 64)
                : (kh + (size_t)s * KV_SIZE + (hidx - 16) * HEAD_DIM + hf * 64);
            // pass 2: recompute and write
            #pragma unroll 4
            for (int j = 0; j < 64; j += 2) {
                float x1a = __half2float(*(const __half*)(rowp + j * 2));
                float x2a = __half2float(*(const __half*)(rowp + (j + 64) * 2));
                float x1b = __half2float(*(const __half*)(rowp + (j + 1) * 2));
                float x2b = __half2float(*(const __half*)(rowp + (j + 65) * 2));
                float2 ca = tab[(size_t)s * 64 + j];
                float2 cb = tab[(size_t)s * 64 + j + 1];
                float va = hf ? (x2a * ca.x + x1a * ca.y) : (x1a * ca.x - x2a * ca.y);
                float vb = hf ? (x2b * cb.x + x1b * cb.y) : (x1b * cb.x - x2b * cb.y);
                *(u32*)(dst + j) = packh(va * inv * wp[j], vb * inv * wp[j + 1]);
            }
        }
    }
}

// ======================= mma.sync flash attention (fp16) =======================
// QK^T: 1-term Qh*Kh;  PV: 1-term Ph*Vh;  K,V compact fp16.
#define AROW 272
#define AQ_BYTES (128 * AROW)
#define AS_K (64 * AROW)
#define AS_STG (2 * AS_K)                // KH | VH
#define A_STG0 AQ_BYTES
#define ATTN_SMEM (AQ_BYTES + 2 * AS_STG)   // 104448

__device__ __forceinline__ void attn_load_kv(
    u32 sdst, const __half* __restrict__ kh, const __half* __restrict__ vh,
    int n0, int kvh, int tid)
{
    #pragma unroll
    for (int i = 0; i < 8; ++i) {
        int c = tid + i * 256;
        int arr = c >> 10;
        int rem = c & 1023;
        int row = rem >> 4, ch = rem & 15;
        const __half* src = (arr == 0) ? kh : vh;
        cp16(sdst + arr * AS_K + row * AROW + ch * 16,
             (const void*)(src + (size_t)(n0 + row) * KV_SIZE + kvh * HEAD_DIM + ch * 8));
    }
}

__global__ __launch_bounds__(256, 1) void attn_mma_kernel(
    const __half* __restrict__ qh, const __half* __restrict__ kh,
    const __half* __restrict__ vh,
    __half* __restrict__ att)
{
    const int h = blockIdx.x;
    const int m0 = (int)(gridDim.y - 1 - blockIdx.y) * 128;
    const int kvh = h >> 1;
    extern __shared__ __align__(16) char sm[];
    const u32 smb = smem_u32(sm);
    const int tid = threadIdx.x, wid = tid >> 5, lane = tid & 31;
    const int gro = lane >> 2, tq = lane & 3;
    const float scale = 0.08838834764831845f;

    // ---- load Q tile (single) ----
    #pragma unroll
    for (int i = 0; i < 8; ++i) {
        int c = tid + i * 256;
        int row = c >> 4, ch = c & 15;
        cp16(smb + row * AROW + ch * 16,
             (const void*)(qh + (size_t)(m0 + row) * Q_SIZE + h * HEAD_DIM + ch * 8));
    }
    CP_COMMIT();

    const int nt = m0 / 64 + 2;
    attn_load_kv(smb + A_STG0, kh, vh, 0, kvh, tid);
    CP_COMMIT();

    u32 qf[8][4];
    {
        CP_WAIT(1);
        __syncthreads();
        const u32 qb = (u32)((wid * 16 + (lane & 15)) * AROW + ((lane >> 4) << 4));
        #pragma unroll
        for (int kb = 0; kb < 8; ++kb)
            ldsm_x4(qf[kb][0], qf[kb][1], qf[kb][2], qf[kb][3], smb + qb + kb * 32);
    }

    float oacc[16][4];
    #pragma unroll
    for (int nd = 0; nd < 16; ++nd)
        #pragma unroll
        for (int e = 0; e < 4; ++e) oacc[nd][e] = 0.0f;
    float mrow0 = -1e30f, mrow1 = -1e30f, lrow0 = 0.0f, lrow1 = 0.0f;

    const int rowg0 = m0 + wid * 16 + gro;

    const u32 kb_base = (u32)(((lane & 7)) * AROW + (((lane >> 3) & 1) << 4));
    const u32 vb_base = (u32)((lane & 15) * AROW + (((lane >> 4) & 1) << 4));

    for (int t = 0; t < nt; ++t) {
        const int n0 = t * 64;
        if (t + 1 < nt) {
            attn_load_kv(smb + A_STG0 + ((t + 1) & 1) * AS_STG, kh, vh,
                         (t + 1) * 64, kvh, tid);
            CP_COMMIT();
            CP_WAIT(1);
        } else {
            CP_WAIT(0);
        }
        __syncthreads();

        const u32 st = smb + A_STG0 + (t & 1) * AS_STG;
        const u32 sKH = st, sVH = st + AS_K;

        // ---- scores S = Qh Kh^T ----
        float sacc[8][4];
        #pragma unroll
        for (int nf = 0; nf < 8; ++nf)
            #pragma unroll
            for (int e = 0; e < 4; ++e) sacc[nf][e] = 0.0f;

        #pragma unroll
        for (int kb = 0; kb < 8; ++kb) {
            u32 bh[8][2];
            #pragma unroll
            for (int nf = 0; nf < 8; ++nf)
                ldsm_x2(bh[nf][0], bh[nf][1], sKH + kb_base + nf * 8 * AROW + kb * 32);
            #pragma unroll
            for (int nf = 0; nf < 8; ++nf)
                mma_f16(sacc[nf], qf[kb], bh[nf]);
        }

        // ---- scale + mask ----
        const bool need_mask = (n0 + 63 > m0);
        #pragma unroll
        for (int nf = 0; nf < 8; ++nf) {
            int c0 = n0 + nf * 8 + tq * 2;
            #pragma unroll
            for (int e = 0; e < 4; ++e) {
                float v = sacc[nf][e] * scale;
                if (need_mask) {
                    int cc = c0 + (e & 1);
                    int rr = rowg0 + ((e >> 1) << 3);
                    if (cc > rr) v = -1e30f;
                }
                sacc[nf][e] = v;
            }
        }

        // ---- online softmax ----
        float mx0 = -1e30f, mx1 = -1e30f;
        #pragma unroll
        for (int nf = 0; nf < 8; ++nf) {
            mx0 = fmaxf(mx0, fmaxf(sacc[nf][0], sacc[nf][1]));
            mx1 = fmaxf(mx1, fmaxf(sacc[nf][2], sacc[nf][3]));
        }
        mx0 = fmaxf(mx0, __shfl_xor_sync(0xffffffffu, mx0, 1));
        mx0 = fmaxf(mx0, __shfl_xor_sync(0xffffffffu, mx0, 2));
        mx1 = fmaxf(mx1, __shfl_xor_sync(0xffffffffu, mx1, 1));
        mx1 = fmaxf(mx1, __shfl_xor_sync(0xffffffffu, mx1, 2));
        float mn0 = fmaxf(mrow0, mx0), mn1 = fmaxf(mrow1, mx1);
        float a0 = __expf(mrow0 - mn0), a1 = __expf(mrow1 - mn1);
        mrow0 = mn0; mrow1 = mn1;

        float sum0 = 0.0f, sum1 = 0.0f;
        #pragma unroll
        for (int nf = 0; nf < 8; ++nf) {
            sacc[nf][0] = __expf(sacc[nf][0] - mn0);
            sacc[nf][1] = __expf(sacc[nf][1] - mn0);
            sacc[nf][2] = __expf(sacc[nf][2] - mn1);
            sacc[nf][3] = __expf(sacc[nf][3] - mn1);
            sum0 += sacc[nf][0] + sacc[nf][1];
            sum1 += sacc[nf][2] + sacc[nf][3];
        }
        sum0 += __shfl_xor_sync(0xffffffffu, sum0, 1);
        sum0 += __shfl_xor_sync(0xffffffffu, sum0, 2);
        sum1 += __shfl_xor_sync(0xffffffffu, sum1, 1);
        sum1 += __shfl_xor_sync(0xffffffffu, sum1, 2);
        lrow0 = lrow0 * a0 + sum0;
        lrow1 = lrow1 * a1 + sum1;

        #pragma unroll
        for (int nd = 0; nd < 16; ++nd) {
            oacc[nd][0] *= a0; oacc[nd][1] *= a0;
            oacc[nd][2] *= a1; oacc[nd][3] *= a1;
        }

        // ---- P -> single fp16 a-frags ----
        u32 pa[4][4];
        #pragma unroll
        for (int kq = 0; kq < 4; ++kq) {
            pa[kq][0] = packh(sacc[2*kq][0],   sacc[2*kq][1]);
            pa[kq][1] = packh(sacc[2*kq][2],   sacc[2*kq][3]);
            pa[kq][2] = packh(sacc[2*kq+1][0], sacc[2*kq+1][1]);
            pa[kq][3] = packh(sacc[2*kq+1][2], sacc[2*kq+1][3]);
        }

        // ---- O += Ph Vh ----
        #pragma unroll
        for (int kq = 0; kq < 4; ++kq) {
            #pragma unroll
            for (int nd = 0; nd < 8; ++nd) {
                u32 b[4];
                ldsm_x4t(b[0], b[1], b[2], b[3], sVH + vb_base + kq * 16 * AROW + nd * 32);
                mma_f16(oacc[2*nd],     pa[kq], &b[0]);
                mma_f16(oacc[2*nd + 1], pa[kq], &b[2]);
            }
        }
        __syncthreads();
    }

    // ---- epilogue: single fp16 ----
    float inv0 = 1.0f / lrow0, inv1 = 1.0f / lrow1;
    #pragma unroll
    for (int nd = 0; nd < 16; ++nd) {
        int col = h * HEAD_DIM + nd * 8 + tq * 2;
        size_t i0 = (size_t)rowg0 * Q_SIZE + col;
        size_t i1 = (size_t)(rowg0 + 8) * Q_SIZE + col;
        *(u32*)&att[i0] = packh(oacc[nd][0] * inv0, oacc[nd][1] * inv0);
        *(u32*)&att[i1] = packh(oacc[nd][2] * inv1, oacc[nd][3] * inv1);
    }
}

// =============================== launch ===============================
extern "C" void kernel_launch(void* const* d_in, const int* in_sizes, int n_in,
                              void* d_out, int out_size)
{
    const int*   positions = (const int*)d_in[0];
    const float* hidden    = (const float*)d_in[1];
    const float* ln_w      = (const float*)d_in[2];
    const float* qkv_w     = (const float*)d_in[3];
    const float* q_norm_w  = (const float*)d_in[4];
    const float* k_norm_w  = (const float*)d_in[5];
    const float* o_w       = (const float*)d_in[6];
    float* out = (float*)d_out;

    __half *p_nh, *p_ah, *p_wqh, *p_woh, *p_qh, *p_kh, *p_vh;
    float2 *p_rope;
    cudaGetSymbolAddress((void**)&p_nh,   g_norm_h);
    cudaGetSymbolAddress((void**)&p_rope, g_rope);
    cudaGetSymbolAddress((void**)&p_qh,   g_q_h);
    cudaGetSymbolAddress((void**)&p_kh,   g_k_h);
    cudaGetSymbolAddress((void**)&p_vh,   g_v_h);
    cudaGetSymbolAddress((void**)&p_ah,   g_att_h);
    cudaGetSymbolAddress((void**)&p_wqh,  g_wq_h);
    cudaGetSymbolAddress((void**)&p_woh,  g_wo_h);

    cudaFuncSetAttribute(gemm_mma_kernel<0>, cudaFuncAttributeMaxDynamicSharedMemorySize, GSMEM);
    cudaFuncSetAttribute(gemm_mma_kernel<1>, cudaFuncAttributeMaxDynamicSharedMemorySize, GSMEM);
    cudaFuncSetAttribute(attn_mma_kernel, cudaFuncAttributeMaxDynamicSharedMemorySize, ATTN_SMEM);

    // 0) weight prep + rope table
    convh_kernel<<<(QKV_COLS * HIDDEN / 4 + 255) / 256, 256>>>(qkv_w, p_wqh, QKV_COLS * HIDDEN / 4);
    convh_kernel<<<(HIDDEN * Q_SIZE / 4 + 255) / 256, 256>>>(o_w, p_woh, HIDDEN * Q_SIZE / 4);
    rope_table_kernel<<<SEQ, 64>>>(positions, p_rope);

    // 1) RMSNorm -> single fp16
    rmsnorm_kernel<<<SEQ, 256>>>(hidden, ln_w, p_nh);

    // 2) QKV projection with fused rope/norm/v-scatter epilogue
    gemm_mma_kernel<1><<<dim3(QKV_COLS / 128, SEQ / 128), 256, GSMEM>>>(
        p_nh, p_wqh, nullptr, SEQ, QKV_COLS, HIDDEN,
        p_rope, q_norm_w, k_norm_w, p_qh, p_kh, p_vh);

    // 3) causal GQA flash attention (1-term QK, 1-term PV) -> single fp16
    attn_mma_kernel<<<dim3(NUM_HEADS, SEQ / 128), 256, ATTN_SMEM>>>(
        p_qh, p_kh, p_vh, p_ah);

    // 4) O projection (fp16 in, fp32 out)
    gemm_mma_kernel<0><<<dim3(HIDDEN / 128, SEQ / 128), 256, GSMEM>>>(
        p_ah, p_woh, out, SEQ, HIDDEN, Q_SIZE,
        nullptr, nullptr, nullptr, nullptr, nullptr, nullptr);
}

// round 17
// speedup vs baseline: 1.0811x; 1.0811x over previous
#include <cuda_runtime.h>
#include <cuda_fp16.h>
#include <cstdint>
#include <math.h>

typedef unsigned int u32;
typedef unsigned long long u64;

#define SEQ 2048
#define HIDDEN 2048
#define NUM_HEADS 16
#define NUM_KV_HEADS 8
#define HEAD_DIM 128
#define Q_SIZE 2048
#define KV_SIZE 1024
#define QKV_COLS 4096
#define V_OFF 3072

// -------- scratch (static device memory; no allocation) --------
__device__ __half g_norm_h[SEQ * HIDDEN];
__device__ __half g_qkv_h[SEQ * QKV_COLS];
__device__ float2 g_rope[SEQ * 64];
__device__ __half g_q_h[SEQ * Q_SIZE];
__device__ __half g_k_h[SEQ * KV_SIZE];
__device__ __half g_att_h[SEQ * Q_SIZE];
__device__ __half g_wq_h[QKV_COLS * HIDDEN];
__device__ __half g_wo_h[HIDDEN * Q_SIZE];

// ======================= helpers =======================
__device__ __forceinline__ u32 smem_u32(const void* p) {
    u32 a;
    asm("{ .reg .u64 t; cvta.to.shared.u64 t, %1; cvt.u32.u64 %0, t; }" : "=r"(a) : "l"(p));
    return a;
}
__device__ __forceinline__ void ldsm_x4(u32& r0, u32& r1, u32& r2, u32& r3, u32 a) {
    asm volatile("ldmatrix.sync.aligned.m8n8.x4.shared.b16 {%0,%1,%2,%3}, [%4];"
                 : "=r"(r0), "=r"(r1), "=r"(r2), "=r"(r3) : "r"(a));
}
__device__ __forceinline__ void ldsm_x2(u32& r0, u32& r1, u32 a) {
    asm volatile("ldmatrix.sync.aligned.m8n8.x2.shared.b16 {%0,%1}, [%2];"
                 : "=r"(r0), "=r"(r1) : "r"(a));
}
__device__ __forceinline__ void ldsm_x4t(u32& r0, u32& r1, u32& r2, u32& r3, u32 a) {
    asm volatile("ldmatrix.sync.aligned.m8n8.x4.trans.shared.b16 {%0,%1,%2,%3}, [%4];"
                 : "=r"(r0), "=r"(r1), "=r"(r2), "=r"(r3) : "r"(a));
}
__device__ __forceinline__ void mma_f16(float* c, const u32* a, const u32* b) {
    asm volatile("mma.sync.aligned.m16n8k16.row.col.f32.f16.f16.f32 "
                 "{%0,%1,%2,%3}, {%4,%5,%6,%7}, {%8,%9}, {%0,%1,%2,%3};"
                 : "+f"(c[0]), "+f"(c[1]), "+f"(c[2]), "+f"(c[3])
                 : "r"(a[0]), "r"(a[1]), "r"(a[2]), "r"(a[3]), "r"(b[0]), "r"(b[1]));
}
#define CP_COMMIT() asm volatile("cp.async.commit_group;" ::: "memory")
#define CP_WAIT(n)  asm volatile("cp.async.wait_group %0;" :: "n"(n) : "memory")
__device__ __forceinline__ void cp16(u32 d, const void* s) {
    asm volatile("cp.async.cg.shared.global [%0], [%1], 16;" :: "r"(d), "l"(s));
}
__device__ __forceinline__ u32 packh(float x, float y) {
    __half2 t = __floats2half2_rn(x, y);
    return *(u32*)&t;
}

// ============ fp32 -> fp16 convert (both weight arrays, one launch) ============
__global__ __launch_bounds__(256) void convh2_kernel(
    const float* __restrict__ x1, __half* __restrict__ y1, int n4a,
    const float* __restrict__ x2, __half* __restrict__ y2, int n4total)
{
    int i = blockIdx.x * 256 + threadIdx.x;
    if (i >= n4total) return;
    const float* x;
    __half* y;
    int k;
    if (i < n4a) { x = x1; y = y1; k = i; }
    else         { x = x2; y = y2; k = i - n4a; }
    float4 v = ((const float4*)x)[k];
    y[4*k+0] = __float2half_rn(v.x);
    y[4*k+1] = __float2half_rn(v.y);
    y[4*k+2] = __float2half_rn(v.z);
    y[4*k+3] = __float2half_rn(v.w);
}

// ======================= RMSNorm -> single fp16 =======================
__global__ __launch_bounds__(256) void rmsnorm_kernel(
    const float* __restrict__ x, const float* __restrict__ w,
    __half* __restrict__ oh)
{
    int row = blockIdx.x;
    int t = threadIdx.x;
    const float4* xr = (const float4*)(x + (size_t)row * HIDDEN);
    float4 v0 = xr[t];
    float4 v1 = xr[t + 256];
    float ss = v0.x*v0.x + v0.y*v0.y + v0.z*v0.z + v0.w*v0.w
             + v1.x*v1.x + v1.y*v1.y + v1.z*v1.z + v1.w*v1.w;
    #pragma unroll
    for (int o = 16; o; o >>= 1) ss += __shfl_xor_sync(0xffffffffu, ss, o);
    __shared__ float wsum[8];
    if ((t & 31) == 0) wsum[t >> 5] = ss;
    __syncthreads();
    float tot = wsum[0] + wsum[1] + wsum[2] + wsum[3]
              + wsum[4] + wsum[5] + wsum[6] + wsum[7];
    float inv = rsqrtf(tot * (1.0f / HIDDEN) + 1e-6f);
    const float4* wr = (const float4*)w;
    float4 w0 = wr[t], w1 = wr[t + 256];
    size_t base = (size_t)row * HIDDEN;
    u32* oh32 = (u32*)(oh + base);
    oh32[t*2]         = packh(v0.x*inv*w0.x, v0.y*inv*w0.y);
    oh32[t*2+1]       = packh(v0.z*inv*w0.z, v0.w*inv*w0.w);
    oh32[(t+256)*2]   = packh(v1.x*inv*w1.x, v1.y*inv*w1.y);
    oh32[(t+256)*2+1] = packh(v1.z*inv*w1.z, v1.w*inv*w1.w);
}

// ============== RoPE cos/sin table: hoisted pow + fast sincos ==============
// Same fp32 angle as before (pos * (float)pow). sincos via double range
// reduction + sincosf: |err| ~1e-7 vs the previous double sincos.
__global__ __launch_bounds__(64) void rope_table_kernel(
    const int* __restrict__ positions, float2* __restrict__ tab)
{
    int j = threadIdx.x;
    float inv_freq = (float)pow(10000.0, -(double)(2 * j) / 128.0);
    const double TWO_PI  = 6.283185307179586476925286766559;
    const double INV_2PI = 0.15915494309189533576888376337251;
    int s0 = blockIdx.x * 32;
    #pragma unroll 4
    for (int k = 0; k < 32; ++k) {
        int s = s0 + k;
        float fr = (float)positions[s] * inv_freq;
        double d = (double)fr;
        double n = rint(d * INV_2PI);
        float r = (float)(d - n * TWO_PI);
        float sn, cs;
        sincosf(r, &sn, &cs);
        tab[s * 64 + j] = make_float2(cs, sn);
    }
}

// ===== mma.sync 1-term fp16 GEMM: C[M,N] = A[M,K] @ B[N,K]^T =====
// CTA tile 128x128, BK=32, 8 warps, cp.async double buffer, occ 2.
#define BK 32
#define LDT 40
#define TILE_B (128 * LDT * 2)
#define STAGE_B (2 * TILE_B)          // A | B = 20480
#define GSMEM (2 * STAGE_B)           // 40960

__device__ __forceinline__ void load_stage_async(
    u32 sdst, const __half* __restrict__ A, const __half* __restrict__ B,
    int m0, int n0, int kc, int K, int tid)
{
    #pragma unroll
    for (int i = 0; i < 4; ++i) {
        int c = tid + i * 256;
        int tile = c >> 9;
        int rem = c & 511;
        int row = rem >> 2;
        int col8 = (rem & 3) * 8;
        const __half* src = tile ? B : A;
        int gr = (tile ? n0 : m0) + row;
        cp16(sdst + tile * TILE_B + row * (LDT * 2) + col8 * 2,
             (const void*)(src + (size_t)gr * K + kc + col8));
    }
}

template<bool F16OUT>
__global__ __launch_bounds__(256, 2) void gemm_mma_kernel(
    const __half* __restrict__ A, const __half* __restrict__ B,
    void* __restrict__ Cv, int M, int N, int K)
{
    extern __shared__ __align__(16) char sm[];
    const u32 smb = smem_u32(sm);
    const int tid = threadIdx.x, wid = tid >> 5, lane = tid & 31;
    const int m0 = blockIdx.y * 128, n0 = blockIdx.x * 128;
    const int wm = wid >> 2, wn = wid & 3;

    float acc[4][4][4];
    #pragma unroll
    for (int a = 0; a < 4; ++a)
        #pragma unroll
        for (int b = 0; b < 4; ++b)
            #pragma unroll
            for (int d = 0; d < 4; ++d) acc[a][b][d] = 0.0f;

    const int NC = K / BK;

    load_stage_async(smb, A, B, m0, n0, 0, K, tid);
    CP_COMMIT();

    const u32 a_base = (u32)((wm * 64 + (lane & 15)) * (LDT * 2));
    const u32 a_koff = (u32)(((lane >> 4) << 3) * 2);
    const u32 b_base = (u32)((wn * 32 + (lane & 7)) * (LDT * 2));
    const u32 b_koff = (u32)((((lane >> 3) & 1) << 3) * 2);

    for (int c = 0; c < NC; ++c) {
        if (c + 1 < NC) {
            load_stage_async(smb + ((c + 1) & 1) * STAGE_B, A, B,
                             m0, n0, (c + 1) * BK, K, tid);
            CP_COMMIT();
            CP_WAIT(1);
        } else {
            CP_WAIT(0);
        }
        __syncthreads();

        const u32 st = smb + (c & 1) * STAGE_B;
        const u32 sA = st, sB = st + TILE_B;

        #pragma unroll
        for (int ks = 0; ks < 2; ++ks) {
            const u32 kb = (u32)(ks * 16 * 2);
            u32 bh[4][2];
            #pragma unroll
            for (int nf = 0; nf < 4; ++nf)
                ldsm_x2(bh[nf][0], bh[nf][1],
                        sB + b_base + nf * 8 * (LDT * 2) + kb + b_koff);
            #pragma unroll
            for (int mh = 0; mh < 2; ++mh) {
                u32 ah[2][4];
                #pragma unroll
                for (int m2 = 0; m2 < 2; ++m2)
                    ldsm_x4(ah[m2][0], ah[m2][1], ah[m2][2], ah[m2][3],
                            sA + a_base + (mh * 2 + m2) * 16 * (LDT * 2) + kb + a_koff);
                #pragma unroll
                for (int m2 = 0; m2 < 2; ++m2)
                    #pragma unroll
                    for (int nf = 0; nf < 4; ++nf)
                        mma_f16(acc[mh * 2 + m2][nf], ah[m2], bh[nf]);
            }
        }
        __syncthreads();
    }

    const int gro = lane >> 2, tq = lane & 3;
    #pragma unroll
    for (int mf = 0; mf < 4; ++mf) {
        #pragma unroll
        for (int nf = 0; nf < 4; ++nf) {
            int r = m0 + wm * 64 + mf * 16 + gro;
            int col = n0 + wn * 32 + nf * 8 + tq * 2;
            if (F16OUT) {
                __half* C = (__half*)Cv;
                *(u32*)&C[(size_t)r * N + col]       = packh(acc[mf][nf][0], acc[mf][nf][1]);
                *(u32*)&C[(size_t)(r + 8) * N + col] = packh(acc[mf][nf][2], acc[mf][nf][3]);
            } else {
                float* C = (float*)Cv;
                *(float2*)&C[(size_t)r * N + col]       = make_float2(acc[mf][nf][0], acc[mf][nf][1]);
                *(float2*)&C[(size_t)(r + 8) * N + col] = make_float2(acc[mf][nf][2], acc[mf][nf][3]);
            }
        }
    }
}

// ====== RoPE + per-head RMSNorm (q,k -> single fp16), reads fp16 qkv ======
__global__ __launch_bounds__(128) void rope_norm_kernel(
    const float2* __restrict__ tab, const __half* __restrict__ qkv,
    const float* __restrict__ qw, const float* __restrict__ kw,
    __half* __restrict__ qh, __half* __restrict__ kh)
{
    int h = blockIdx.x;
    int s = blockIdx.y;
    int i = threadIdx.x;
    bool isq = h < NUM_HEADS;
    int col = isq ? h * HEAD_DIM : Q_SIZE + (h - NUM_HEADS) * HEAD_DIM;

    __shared__ float xv[HEAD_DIM];
    __shared__ float wsum[4];
    float x = __half2float(qkv[(size_t)s * QKV_COLS + col + i]);
    xv[i] = x;
    __syncthreads();

    int j = i & 63;
    float2 cssn = tab[s * 64 + j];
    float cs = cssn.x, sn = cssn.y;
    float x1 = xv[j], x2 = xv[j + 64];
    float val = (i < 64) ? (x1 * cs - x2 * sn) : (x2 * cs + x1 * sn);

    float ss = val * val;
    #pragma unroll
    for (int o = 16; o; o >>= 1) ss += __shfl_xor_sync(0xffffffffu, ss, o);
    if ((i & 31) == 0) wsum[i >> 5] = ss;
    __syncthreads();
    float tot = wsum[0] + wsum[1] + wsum[2] + wsum[3];
    float inv = rsqrtf(tot * (1.0f / HEAD_DIM) + 1e-6f);
    float wgt = isq ? qw[i] : kw[i];
    float o = val * inv * wgt;
    if (isq) qh[(size_t)s * Q_SIZE + h * HEAD_DIM + i] = __float2half_rn(o);
    else     kh[(size_t)s * KV_SIZE + (h - NUM_HEADS) * HEAD_DIM + i] = __float2half_rn(o);
}

// ======================= mma.sync flash attention (fp16) =======================
// QK^T: 1-term Qh*Kh;  PV: 1-term Ph*Vh;  V read in-place from qkv_h.
#define AROW 272
#define AQ_BYTES (128 * AROW)
#define AS_K (64 * AROW)
#define AS_STG (2 * AS_K)                // KH | VH
#define A_STG0 AQ_BYTES
#define ATTN_SMEM (AQ_BYTES + 2 * AS_STG)   // 104448

__device__ __forceinline__ void attn_load_kv(
    u32 sdst, const __half* __restrict__ kh, const __half* __restrict__ qkvh,
    int n0, int kvh, int tid)
{
    #pragma unroll
    for (int i = 0; i < 8; ++i) {
        int c = tid + i * 256;
        int arr = c >> 10;
        int rem = c & 1023;
        int row = rem >> 4, ch = rem & 15;
        const void* src;
        if (arr == 0)
            src = (const void*)(kh + (size_t)(n0 + row) * KV_SIZE + kvh * HEAD_DIM + ch * 8);
        else
            src = (const void*)(qkvh + (size_t)(n0 + row) * QKV_COLS + V_OFF + kvh * HEAD_DIM + ch * 8);
        cp16(sdst + arr * AS_K + row * AROW + ch * 16, src);
    }
}

__global__ __launch_bounds__(256, 1) void attn_mma_kernel(
    const __half* __restrict__ qh, const __half* __restrict__ kh,
    const __half* __restrict__ qkvh,
    __half* __restrict__ att)
{
    const int h = blockIdx.x;
    const int m0 = (int)(gridDim.y - 1 - blockIdx.y) * 128;
    const int kvh = h >> 1;
    extern __shared__ __align__(16) char sm[];
    const u32 smb = smem_u32(sm);
    const int tid = threadIdx.x, wid = tid >> 5, lane = tid & 31;
    const int gro = lane >> 2, tq = lane & 3;
    const float scale = 0.08838834764831845f;

    // ---- load Q tile (single) ----
    #pragma unroll
    for (int i = 0; i < 8; ++i) {
        int c = tid + i * 256;
        int row = c >> 4, ch = c & 15;
        cp16(smb + row * AROW + ch * 16,
             (const void*)(qh + (size_t)(m0 + row) * Q_SIZE + h * HEAD_DIM + ch * 8));
    }
    CP_COMMIT();

    const int nt = m0 / 64 + 2;
    attn_load_kv(smb + A_STG0, kh, qkvh, 0, kvh, tid);
    CP_COMMIT();

    u32 qf[8][4];
    {
        CP_WAIT(1);
        __syncthreads();
        const u32 qb = (u32)((wid * 16 + (lane & 15)) * AROW + ((lane >> 4) << 4));
        #pragma unroll
        for (int kb = 0; kb < 8; ++kb)
            ldsm_x4(qf[kb][0], qf[kb][1], qf[kb][2], qf[kb][3], smb + qb + kb * 32);
    }

    float oacc[16][4];
    #pragma unroll
    for (int nd = 0; nd < 16; ++nd)
        #pragma unroll
        for (int e = 0; e < 4; ++e) oacc[nd][e] = 0.0f;
    float mrow0 = -1e30f, mrow1 = -1e30f, lrow0 = 0.0f, lrow1 = 0.0f;

    const int rowg0 = m0 + wid * 16 + gro;

    const u32 kb_base = (u32)(((lane & 7)) * AROW + (((lane >> 3) & 1) << 4));
    const u32 vb_base = (u32)((lane & 15) * AROW + (((lane >> 4) & 1) << 4));

    for (int t = 0; t < nt; ++t) {
        const int n0 = t * 64;
        if (t + 1 < nt) {
            attn_load_kv(smb + A_STG0 + ((t + 1) & 1) * AS_STG, kh, qkvh,
                         (t + 1) * 64, kvh, tid);
            CP_COMMIT();
            CP_WAIT(1);
        } else {
            CP_WAIT(0);
        }
        __syncthreads();

        const u32 st = smb + A_STG0 + (t & 1) * AS_STG;
        const u32 sKH = st, sVH = st + AS_K;

        // ---- scores S = Qh Kh^T ----
        float sacc[8][4];
        #pragma unroll
        for (int nf = 0; nf < 8; ++nf)
            #pragma unroll
            for (int e = 0; e < 4; ++e) sacc[nf][e] = 0.0f;

        #pragma unroll
        for (int kb = 0; kb < 8; ++kb) {
            u32 bh[8][2];
            #pragma unroll
            for (int nf = 0; nf < 8; ++nf)
                ldsm_x2(bh[nf][0], bh[nf][1], sKH + kb_base + nf * 8 * AROW + kb * 32);
            #pragma unroll
            for (int nf = 0; nf < 8; ++nf)
                mma_f16(sacc[nf], qf[kb], bh[nf]);
        }

        // ---- scale + mask ----
        const bool need_mask = (n0 + 63 > m0);
        #pragma unroll
        for (int nf = 0; nf < 8; ++nf) {
            int c0 = n0 + nf * 8 + tq * 2;
            #pragma unroll
            for (int e = 0; e < 4; ++e) {
                float v = sacc[nf][e] * scale;
                if (need_mask) {
                    int cc = c0 + (e & 1);
                    int rr = rowg0 + ((e >> 1) << 3);
                    if (cc > rr) v = -1e30f;
                }
                sacc[nf][e] = v;
            }
        }

        // ---- online softmax ----
        float mx0 = -1e30f, mx1 = -1e30f;
        #pragma unroll
        for (int nf = 0; nf < 8; ++nf) {
            mx0 = fmaxf(mx0, fmaxf(sacc[nf][0], sacc[nf][1]));
            mx1 = fmaxf(mx1, fmaxf(sacc[nf][2], sacc[nf][3]));
        }
        mx0 = fmaxf(mx0, __shfl_xor_sync(0xffffffffu, mx0, 1));
        mx0 = fmaxf(mx0, __shfl_xor_sync(0xffffffffu, mx0, 2));
        mx1 = fmaxf(mx1, __shfl_xor_sync(0xffffffffu, mx1, 1));
        mx1 = fmaxf(mx1, __shfl_xor_sync(0xffffffffu, mx1, 2));
        float mn0 = fmaxf(mrow0, mx0), mn1 = fmaxf(mrow1, mx1);
        float a0 = __expf(mrow0 - mn0), a1 = __expf(mrow1 - mn1);
        mrow0 = mn0; mrow1 = mn1;

        float sum0 = 0.0f, sum1 = 0.0f;
        #pragma unroll
        for (int nf = 0; nf < 8; ++nf) {
            sacc[nf][0] = __expf(sacc[nf][0] - mn0);
            sacc[nf][1] = __expf(sacc[nf][1] - mn0);
            sacc[nf][2] = __expf(sacc[nf][2] - mn1);
            sacc[nf][3] = __expf(sacc[nf][3] - mn1);
            sum0 += sacc[nf][0] + sacc[nf][1];
            sum1 += sacc[nf][2] + sacc[nf][3];
        }
        sum0 += __shfl_xor_sync(0xffffffffu, sum0, 1);
        sum0 += __shfl_xor_sync(0xffffffffu, sum0, 2);
        sum1 += __shfl_xor_sync(0xffffffffu, sum1, 1);
        sum1 += __shfl_xor_sync(0xffffffffu, sum1, 2);
        lrow0 = lrow0 * a0 + sum0;
        lrow1 = lrow1 * a1 + sum1;

        #pragma unroll
        for (int nd = 0; nd < 16; ++nd) {
            oacc[nd][0] *= a0; oacc[nd][1] *= a0;
            oacc[nd][2] *= a1; oacc[nd][3] *= a1;
        }

        // ---- P -> single fp16 a-frags ----
        u32 pa[4][4];
        #pragma unroll
        for (int kq = 0; kq < 4; ++kq) {
            pa[kq][0] = packh(sacc[2*kq][0],   sacc[2*kq][1]);
            pa[kq][1] = packh(sacc[2*kq][2],   sacc[2*kq][3]);
            pa[kq][2] = packh(sacc[2*kq+1][0], sacc[2*kq+1][1]);
            pa[kq][3] = packh(sacc[2*kq+1][2], sacc[2*kq+1][3]);
        }

        // ---- O += Ph Vh ----
        #pragma unroll
        for (int kq = 0; kq < 4; ++kq) {
            #pragma unroll
            for (int nd = 0; nd < 8; ++nd) {
                u32 b[4];
                ldsm_x4t(b[0], b[1], b[2], b[3], sVH + vb_base + kq * 16 * AROW + nd * 32);
                mma_f16(oacc[2*nd],     pa[kq], &b[0]);
                mma_f16(oacc[2*nd + 1], pa[kq], &b[2]);
            }
        }
        __syncthreads();
    }

    // ---- epilogue: single fp16 ----
    float inv0 = 1.0f / lrow0, inv1 = 1.0f / lrow1;
    #pragma unroll
    for (int nd = 0; nd < 16; ++nd) {
        int col = h * HEAD_DIM + nd * 8 + tq * 2;
        size_t i0 = (size_t)rowg0 * Q_SIZE + col;
        size_t i1 = (size_t)(rowg0 + 8) * Q_SIZE + col;
        *(u32*)&att[i0] = packh(oacc[nd][0] * inv0, oacc[nd][1] * inv0);
        *(u32*)&att[i1] = packh(oacc[nd][2] * inv1, oacc[nd][3] * inv1);
    }
}

// =============================== launch ===============================
extern "C" void kernel_launch(void* const* d_in, const int* in_sizes, int n_in,
                              void* d_out, int out_size)
{
    const int*   positions = (const int*)d_in[0];
    const float* hidden    = (const float*)d_in[1];
    const float* ln_w      = (const float*)d_in[2];
    const float* qkv_w     = (const float*)d_in[3];
    const float* q_norm_w  = (const float*)d_in[4];
    const float* k_norm_w  = (const float*)d_in[5];
    const float* o_w       = (const float*)d_in[6];
    float* out = (float*)d_out;

    __half *p_nh, *p_qkvh, *p_ah, *p_wqh, *p_woh, *p_qh, *p_kh;
    float2 *p_rope;
    cudaGetSymbolAddress((void**)&p_nh,   g_norm_h);
    cudaGetSymbolAddress((void**)&p_qkvh, g_qkv_h);
    cudaGetSymbolAddress((void**)&p_rope, g_rope);
    cudaGetSymbolAddress((void**)&p_qh,   g_q_h);
    cudaGetSymbolAddress((void**)&p_kh,   g_k_h);
    cudaGetSymbolAddress((void**)&p_ah,   g_att_h);
    cudaGetSymbolAddress((void**)&p_wqh,  g_wq_h);
    cudaGetSymbolAddress((void**)&p_woh,  g_wo_h);

    cudaFuncSetAttribute(gemm_mma_kernel<true>,  cudaFuncAttributeMaxDynamicSharedMemorySize, GSMEM);
    cudaFuncSetAttribute(gemm_mma_kernel<false>, cudaFuncAttributeMaxDynamicSharedMemorySize, GSMEM);
    cudaFuncSetAttribute(attn_mma_kernel, cudaFuncAttributeMaxDynamicSharedMemorySize, ATTN_SMEM);

    // 0) weight prep (single launch) + rope table
    const int n4a = QKV_COLS * HIDDEN / 4;
    const int n4t = n4a + HIDDEN * Q_SIZE / 4;
    convh2_kernel<<<(n4t + 255) / 256, 256>>>(qkv_w, p_wqh, n4a, o_w, p_woh, n4t);
    rope_table_kernel<<<SEQ / 32, 64>>>(positions, p_rope);

    // 1) RMSNorm -> single fp16
    rmsnorm_kernel<<<SEQ, 256>>>(hidden, ln_w, p_nh);

    // 2) QKV projection (fp16 in, fp16 out)
    gemm_mma_kernel<true><<<dim3(QKV_COLS / 128, SEQ / 128), 256, GSMEM>>>(
        p_nh, p_wqh, (void*)p_qkvh, SEQ, QKV_COLS, HIDDEN);

    // 3) RoPE + q/k RMSNorm (q,k single fp16; V stays in qkv_h)
    rope_norm_kernel<<<dim3(NUM_HEADS + NUM_KV_HEADS, SEQ), 128>>>(
        p_rope, p_qkvh, q_norm_w, k_norm_w, p_qh, p_kh);

    // 4) causal GQA flash attention (1-term QK, 1-term PV) -> single fp16
    attn_mma_kernel<<<dim3(NUM_HEADS, SEQ / 128), 256, ATTN_SMEM>>>(
        p_qh, p_kh, p_qkvh, p_ah);

    // 5) O projection (fp16 in, fp32 out)
    gemm_mma_kernel<false><<<dim3(HIDDEN / 128, SEQ / 128), 256, GSMEM>>>(
        p_ah, p_woh, (void*)out, SEQ, HIDDEN, Q_SIZE);
}